// round 2
// baseline (speedup 1.0000x reference)
#include <cuda_runtime.h>
#include <cuda_bf16.h>

// ---------------------------------------------------------------------------
// TernaryCNN baseline: ternarize -> 4x(conv3x3 + BN(batch) + relu + pool2) ->
// FC(32768->1024)+relu -> FC(1024->1000)
// Conv bias cancels exactly under training-mode BN (mean subtraction), so it
// is skipped. All reductions are deterministic (fixed-shape tree reductions).
// ---------------------------------------------------------------------------

#define N_BATCH 32
#define NB_RED 512          // partial blocks for global reductions
#define BN_NB 64            // partial blocks per channel for BN stats

// -------------------- device scratch (static, no allocs) -------------------
__device__ float g_conv[33554432];     // largest conv output: 32*64*128*128
__device__ float g_pool[8388608];      // largest pooled output: 32*64*64*64
__device__ float g_tw1[1728];
__device__ float g_tw2[73728];
__device__ float g_tw3[294912];
__device__ float g_tw4[1179648];
__device__ float g_tfw1[33554432];     // 1024*32768
__device__ float g_tfw2[1024000];      // 1000*1024
__device__ float g_fc1[32 * 1024];
__device__ float g_fc1part[16 * 32 * 1024];
__device__ float g_part1[NB_RED];
__device__ float g_part2[NB_RED];
__device__ float g_scal[4];            // [0]=delta [1]=alpha [2]=mean|w|
__device__ float g_bnp1[512 * BN_NB];
__device__ float g_bnp2[512 * BN_NB];
__device__ float g_bnscale[512];
__device__ float g_bnshift[512];

// ----------------------------- ternarize -----------------------------------
__global__ void abs_sum_kernel(const float* __restrict__ w, long n, float* __restrict__ part) {
    __shared__ float sh[256];
    float a = 0.f;
    for (long i = (long)blockIdx.x * 256 + threadIdx.x; i < n; i += (long)NB_RED * 256)
        a += fabsf(w[i]);
    sh[threadIdx.x] = a; __syncthreads();
    for (int o = 128; o > 0; o >>= 1) {
        if (threadIdx.x < o) sh[threadIdx.x] += sh[threadIdx.x + o];
        __syncthreads();
    }
    if (threadIdx.x == 0) part[blockIdx.x] = sh[0];
}

__global__ void delta_final_kernel(const float* __restrict__ part, float inv_n, float* __restrict__ scal) {
    __shared__ float sh[256];
    float a = part[threadIdx.x] + part[threadIdx.x + 256];
    sh[threadIdx.x] = a; __syncthreads();
    for (int o = 128; o > 0; o >>= 1) {
        if (threadIdx.x < o) sh[threadIdx.x] += sh[threadIdx.x + o];
        __syncthreads();
    }
    if (threadIdx.x == 0) {
        float mean = sh[0] * inv_n;
        scal[0] = 0.7f * mean;
        scal[2] = mean;
    }
}

__global__ void masked_sum_kernel(const float* __restrict__ w, long n, const float* __restrict__ scal,
                                  float* __restrict__ p1, float* __restrict__ p2) {
    __shared__ float sh1[256], sh2[256];
    const float delta = scal[0];
    float s = 0.f, c = 0.f;
    for (long i = (long)blockIdx.x * 256 + threadIdx.x; i < n; i += (long)NB_RED * 256) {
        float v = fabsf(w[i]);
        if (v > delta) { s += v; c += 1.f; }
    }
    sh1[threadIdx.x] = s; sh2[threadIdx.x] = c; __syncthreads();
    for (int o = 128; o > 0; o >>= 1) {
        if (threadIdx.x < o) { sh1[threadIdx.x] += sh1[threadIdx.x + o]; sh2[threadIdx.x] += sh2[threadIdx.x + o]; }
        __syncthreads();
    }
    if (threadIdx.x == 0) { p1[blockIdx.x] = sh1[0]; p2[blockIdx.x] = sh2[0]; }
}

__global__ void alpha_final_kernel(const float* __restrict__ p1, const float* __restrict__ p2,
                                   float* __restrict__ scal) {
    __shared__ float sh1[256], sh2[256];
    sh1[threadIdx.x] = p1[threadIdx.x] + p1[threadIdx.x + 256];
    sh2[threadIdx.x] = p2[threadIdx.x] + p2[threadIdx.x + 256];
    __syncthreads();
    for (int o = 128; o > 0; o >>= 1) {
        if (threadIdx.x < o) { sh1[threadIdx.x] += sh1[threadIdx.x + o]; sh2[threadIdx.x] += sh2[threadIdx.x + o]; }
        __syncthreads();
    }
    if (threadIdx.x == 0)
        scal[1] = (sh2[0] > 0.f) ? (sh1[0] / sh2[0]) : scal[2];
}

__global__ void tern_write_kernel(const float* __restrict__ w, long n, const float* __restrict__ scal,
                                  float* __restrict__ out) {
    const float d = scal[0], a = scal[1];
    for (long i = (long)blockIdx.x * 256 + threadIdx.x; i < n; i += (long)gridDim.x * 256) {
        float v = w[i];
        out[i] = (v > d) ? a : ((v < -d) ? -a : 0.f);
    }
}

// ------------------------------- conv3x3 -----------------------------------
// TILE x TILE spatial tile, (TILE/2)^2 threads, each thread 2x2 px x 8 co.
template <int TILE>
__global__ void conv3x3_kernel(const float* __restrict__ in, const float* __restrict__ wt,
                               float* __restrict__ out, int CI, int CO, int H, int W) {
    constexpr int TD = TILE / 2;
    constexpr int NT = TD * TD;
    __shared__ float s_in[TILE + 2][TILE + 4];
    __shared__ float s_w[8][9];

    const int cogs = CO >> 3;
    const int n = blockIdx.z / cogs;
    const int cog = blockIdx.z % cogs;
    const int h0 = blockIdx.y * TILE;
    const int w0 = blockIdx.x * TILE;
    const int tid = threadIdx.y * TD + threadIdx.x;
    const long HW = (long)H * W;

    float acc[8][4];
#pragma unroll
    for (int j = 0; j < 8; j++)
#pragma unroll
        for (int p = 0; p < 4; p++) acc[j][p] = 0.f;

    for (int ci = 0; ci < CI; ci++) {
        const float* ip = in + ((long)n * CI + ci) * HW;
        for (int idx = tid; idx < (TILE + 2) * (TILE + 2); idx += NT) {
            int r = idx / (TILE + 2), c = idx % (TILE + 2);
            int gh = h0 - 1 + r, gw = w0 - 1 + c;
            float v = 0.f;
            if (gh >= 0 && gh < H && gw >= 0 && gw < W) v = ip[(long)gh * W + gw];
            s_in[r][c] = v;
        }
        for (int idx = tid; idx < 72; idx += NT) {
            int j = idx / 9, k = idx % 9;
            s_w[j][k] = wt[((long)(cog * 8 + j) * CI + ci) * 9 + k];
        }
        __syncthreads();

        float v[4][4];
        const int r0 = threadIdx.y * 2, c0 = threadIdx.x * 2;
#pragma unroll
        for (int r = 0; r < 4; r++)
#pragma unroll
            for (int c = 0; c < 4; c++) v[r][c] = s_in[r0 + r][c0 + c];

#pragma unroll
        for (int j = 0; j < 8; j++) {
            float w00 = s_w[j][0], w01 = s_w[j][1], w02 = s_w[j][2];
            float w10 = s_w[j][3], w11 = s_w[j][4], w12 = s_w[j][5];
            float w20 = s_w[j][6], w21 = s_w[j][7], w22 = s_w[j][8];
#pragma unroll
            for (int dy = 0; dy < 2; dy++)
#pragma unroll
                for (int dx = 0; dx < 2; dx++) {
                    acc[j][dy * 2 + dx] +=
                        v[dy][dx] * w00 + v[dy][dx + 1] * w01 + v[dy][dx + 2] * w02 +
                        v[dy + 1][dx] * w10 + v[dy + 1][dx + 1] * w11 + v[dy + 1][dx + 2] * w12 +
                        v[dy + 2][dx] * w20 + v[dy + 2][dx + 1] * w21 + v[dy + 2][dx + 2] * w22;
                }
        }
        __syncthreads();
    }

    const int r0 = threadIdx.y * 2, c0 = threadIdx.x * 2;
#pragma unroll
    for (int j = 0; j < 8; j++) {
        const long ob = ((long)n * CO + cog * 8 + j) * HW;
#pragma unroll
        for (int dy = 0; dy < 2; dy++)
#pragma unroll
            for (int dx = 0; dx < 2; dx++) {
                int h = h0 + r0 + dy, w = w0 + c0 + dx;
                if (h < H && w < W) out[ob + (long)h * W + w] = acc[j][dy * 2 + dx];
            }
    }
}

// ------------------------------ batchnorm ----------------------------------
__global__ void bn_partial_kernel(const float* __restrict__ y, int C, int HW,
                                  float* __restrict__ p1, float* __restrict__ p2) {
    __shared__ float sh1[256], sh2[256];
    const int c = blockIdx.x;
    float s = 0.f, s2 = 0.f;
    for (int n = 0; n < N_BATCH; n++) {
        const float* yp = y + ((long)n * C + c) * HW;
        for (int p = blockIdx.y * 256 + threadIdx.x; p < HW; p += BN_NB * 256) {
            float v = yp[p];
            s += v; s2 += v * v;
        }
    }
    sh1[threadIdx.x] = s; sh2[threadIdx.x] = s2; __syncthreads();
    for (int o = 128; o > 0; o >>= 1) {
        if (threadIdx.x < o) { sh1[threadIdx.x] += sh1[threadIdx.x + o]; sh2[threadIdx.x] += sh2[threadIdx.x + o]; }
        __syncthreads();
    }
    if (threadIdx.x == 0) {
        p1[c * BN_NB + blockIdx.y] = sh1[0];
        p2[c * BN_NB + blockIdx.y] = sh2[0];
    }
}

__global__ void bn_final_kernel(const float* __restrict__ p1, const float* __restrict__ p2, float invM,
                                const float* __restrict__ gamma, const float* __restrict__ beta,
                                float* __restrict__ scale, float* __restrict__ shift) {
    __shared__ float sh1[64], sh2[64];
    const int c = blockIdx.x;
    sh1[threadIdx.x] = p1[c * BN_NB + threadIdx.x];
    sh2[threadIdx.x] = p2[c * BN_NB + threadIdx.x];
    __syncthreads();
    for (int o = 32; o > 0; o >>= 1) {
        if (threadIdx.x < o) { sh1[threadIdx.x] += sh1[threadIdx.x + o]; sh2[threadIdx.x] += sh2[threadIdx.x + o]; }
        __syncthreads();
    }
    if (threadIdx.x == 0) {
        float mean = sh1[0] * invM;
        float var = sh2[0] * invM - mean * mean;
        float istd = rsqrtf(var + 1e-5f);
        float sc = gamma[c] * istd;
        scale[c] = sc;
        shift[c] = beta[c] - mean * sc;
    }
}

__global__ void bn_relu_pool_kernel(const float* __restrict__ y, const float* __restrict__ scale,
                                    const float* __restrict__ shift, float* __restrict__ out,
                                    int C, int H, int W, long total) {
    long idx = (long)blockIdx.x * 256 + threadIdx.x;
    if (idx >= total) return;
    const int W2 = W >> 1, H2 = H >> 1;
    int wo = (int)(idx % W2);
    long t = idx / W2;
    int ho = (int)(t % H2); t /= H2;
    int c = (int)(t % C);
    int n = (int)(t / C);
    const float* yp = y + (((long)n * C + c) * H + 2 * ho) * W + 2 * wo;
    float sc = scale[c], sh = shift[c];
    float a = fmaxf(sc * yp[0] + sh, sc * yp[1] + sh);
    float b = fmaxf(sc * yp[W] + sh, sc * yp[W + 1] + sh);
    out[idx] = fmaxf(fmaxf(a, b), 0.f);
}

// --------------------------------- FC --------------------------------------
// FC1: split-K GEMM. grid (O/64, 16 k-splits), block 256. Deterministic:
// each block writes its own partial slab, reduced in fc1_post_kernel.
__global__ void fc1_partial_kernel(const float* __restrict__ x, const float* __restrict__ w,
                                   float* __restrict__ part) {
    __shared__ float s_w[64][33];
    __shared__ __align__(16) float s_x[32][34];
    const int K = 32768;
    const int o0 = blockIdx.x * 64;
    const int k0 = blockIdx.y * 2048;
    const int tid = threadIdx.x;
    const int tx = tid & 15;   // batch pair group: b = tx*2 + {0,1}
    const int ty = tid >> 4;   // output group: o = o0 + ty*4 + {0..3}

    float acc[4][2];
#pragma unroll
    for (int i = 0; i < 4; i++) { acc[i][0] = 0.f; acc[i][1] = 0.f; }

    for (int kk = k0; kk < k0 + 2048; kk += 32) {
#pragma unroll
        for (int t = 0; t < 8; t++) {
            int idx = tid + t * 256;
            int row = idx >> 5, col = idx & 31;
            s_w[row][col] = w[(long)(o0 + row) * K + kk + col];
        }
#pragma unroll
        for (int t = 0; t < 4; t++) {
            int idx = tid + t * 256;
            int b = idx >> 5, col = idx & 31;
            s_x[col][b] = x[(long)b * K + kk + col];
        }
        __syncthreads();
#pragma unroll
        for (int j = 0; j < 32; j++) {
            float2 xb = *(const float2*)&s_x[j][tx * 2];
#pragma unroll
            for (int i = 0; i < 4; i++) {
                float wv = s_w[ty * 4 + i][j];
                acc[i][0] += wv * xb.x;
                acc[i][1] += wv * xb.y;
            }
        }
        __syncthreads();
    }
#pragma unroll
    for (int i = 0; i < 4; i++)
#pragma unroll
        for (int p = 0; p < 2; p++)
            part[((long)blockIdx.y * 32 + tx * 2 + p) * 1024 + o0 + ty * 4 + i] = acc[i][p];
}

__global__ void fc1_post_kernel(const float* __restrict__ part, const float* __restrict__ bias,
                                float* __restrict__ out) {
    int idx = blockIdx.x * 256 + threadIdx.x;   // 32*1024
    if (idx >= 32 * 1024) return;
    int o = idx & 1023;
    float s = 0.f;
#pragma unroll
    for (int ks = 0; ks < 16; ks++) s += part[(long)ks * 32 * 1024 + idx];
    out[idx] = fmaxf(s + bias[o], 0.f);
}

__global__ void fc2_kernel(const float* __restrict__ x, const float* __restrict__ w,
                           const float* __restrict__ bias, float* __restrict__ out) {
    int gw = (blockIdx.x * 256 + threadIdx.x) >> 5;
    int lane = threadIdx.x & 31;
    if (gw >= 32 * 1000) return;
    int b = gw / 1000, o = gw % 1000;
    float a = 0.f;
    for (int k = lane; k < 1024; k += 32)
        a += x[b * 1024 + k] * w[o * 1024 + k];
#pragma unroll
    for (int off = 16; off; off >>= 1) a += __shfl_down_sync(0xffffffffu, a, off);
    if (lane == 0) out[b * 1000 + o] = a + bias[o];
}

// ------------------------------- host side ---------------------------------
static void ternarize(const float* w, long n, float* out) {
    float* p1; float* p2; float* sc;
    cudaGetSymbolAddress((void**)&p1, g_part1);
    cudaGetSymbolAddress((void**)&p2, g_part2);
    cudaGetSymbolAddress((void**)&sc, g_scal);
    abs_sum_kernel<<<NB_RED, 256>>>(w, n, p1);
    delta_final_kernel<<<1, 256>>>(p1, 1.0f / (float)n, sc);
    masked_sum_kernel<<<NB_RED, 256>>>(w, n, sc, p1, p2);
    alpha_final_kernel<<<1, 256>>>(p1, p2, sc);
    int grid = (int)((n + 256 * 8 - 1) / (256 * 8));
    if (grid > 4096) grid = 4096;
    if (grid < 1) grid = 1;
    tern_write_kernel<<<grid, 256>>>(w, n, sc, out);
}

static void conv_block(const float* in, const float* tw, const float* gamma, const float* beta,
                       float* conv_buf, float* pool_buf, int CI, int CO, int H, int W) {
    float* bp1; float* bp2; float* bsc; float* bsh;
    cudaGetSymbolAddress((void**)&bp1, g_bnp1);
    cudaGetSymbolAddress((void**)&bp2, g_bnp2);
    cudaGetSymbolAddress((void**)&bsc, g_bnscale);
    cudaGetSymbolAddress((void**)&bsh, g_bnshift);

    if (H >= 32) {
        dim3 grid(W / 32, H / 32, N_BATCH * (CO / 8));
        dim3 blk(16, 16);
        conv3x3_kernel<32><<<grid, blk>>>(in, tw, conv_buf, CI, CO, H, W);
    } else {
        dim3 grid(W / 16, H / 16, N_BATCH * (CO / 8));
        dim3 blk(8, 8);
        conv3x3_kernel<16><<<grid, blk>>>(in, tw, conv_buf, CI, CO, H, W);
    }

    const int HW = H * W;
    bn_partial_kernel<<<dim3(CO, BN_NB), 256>>>(conv_buf, CO, HW, bp1, bp2);
    bn_final_kernel<<<CO, 64>>>(bp1, bp2, 1.0f / ((float)N_BATCH * HW), gamma, beta, bsc, bsh);

    long total = (long)N_BATCH * CO * (H / 2) * (W / 2);
    int pgrid = (int)((total + 255) / 256);
    bn_relu_pool_kernel<<<pgrid, 256>>>(conv_buf, bsc, bsh, pool_buf, CO, H, W, total);
}

extern "C" void kernel_launch(void* const* d_in, const int* in_sizes, int n_in,
                              void* d_out, int out_size) {
    const float* x   = (const float*)d_in[0];
    const float* w1  = (const float*)d_in[1];
    const float* g1  = (const float*)d_in[3];
    const float* be1 = (const float*)d_in[4];
    const float* w2  = (const float*)d_in[5];
    const float* g2  = (const float*)d_in[7];
    const float* be2 = (const float*)d_in[8];
    const float* w3  = (const float*)d_in[9];
    const float* g3  = (const float*)d_in[11];
    const float* be3 = (const float*)d_in[12];
    const float* w4  = (const float*)d_in[13];
    const float* g4  = (const float*)d_in[15];
    const float* be4 = (const float*)d_in[16];
    const float* fw1 = (const float*)d_in[17];
    const float* fb1 = (const float*)d_in[18];
    const float* fw2 = (const float*)d_in[19];
    const float* fb2 = (const float*)d_in[20];
    float* out = (float*)d_out;

    float *p_conv, *p_pool, *p_tw1, *p_tw2, *p_tw3, *p_tw4, *p_tfw1, *p_tfw2;
    float *p_fc1, *p_fc1part;
    cudaGetSymbolAddress((void**)&p_conv, g_conv);
    cudaGetSymbolAddress((void**)&p_pool, g_pool);
    cudaGetSymbolAddress((void**)&p_tw1, g_tw1);
    cudaGetSymbolAddress((void**)&p_tw2, g_tw2);
    cudaGetSymbolAddress((void**)&p_tw3, g_tw3);
    cudaGetSymbolAddress((void**)&p_tw4, g_tw4);
    cudaGetSymbolAddress((void**)&p_tfw1, g_tfw1);
    cudaGetSymbolAddress((void**)&p_tfw2, g_tfw2);
    cudaGetSymbolAddress((void**)&p_fc1, g_fc1);
    cudaGetSymbolAddress((void**)&p_fc1part, g_fc1part);

    // 1) ternarize all weight tensors
    ternarize(w1, (long)in_sizes[1], p_tw1);
    ternarize(w2, (long)in_sizes[5], p_tw2);
    ternarize(w3, (long)in_sizes[9], p_tw3);
    ternarize(w4, (long)in_sizes[13], p_tw4);
    ternarize(fw1, (long)in_sizes[17], p_tfw1);
    ternarize(fw2, (long)in_sizes[19], p_tfw2);

    // 2) conv blocks (bias cancelled by batch-stat BN)
    conv_block(x,      p_tw1, g1, be1, p_conv, p_pool, 3,   64,  128, 128);
    conv_block(p_pool, p_tw2, g2, be2, p_conv, p_pool, 64,  128, 64,  64);
    conv_block(p_pool, p_tw3, g3, be3, p_conv, p_pool, 128, 256, 32,  32);
    conv_block(p_pool, p_tw4, g4, be4, p_conv, p_pool, 256, 512, 16,  16);

    // 3) FC1 (split-K, deterministic partial reduce) + relu
    fc1_partial_kernel<<<dim3(16, 16), 256>>>(p_pool, p_tfw1, p_fc1part);
    fc1_post_kernel<<<(32 * 1024 + 255) / 256, 256>>>(p_fc1part, fb1, p_fc1);

    // 4) FC2 -> output
    fc2_kernel<<<(32 * 1000 * 32 + 255) / 256, 256>>>(p_fc1, p_tfw2, fb2, out);
}

// round 4
// speedup vs baseline: 2.0732x; 2.0732x over previous
#include <cuda_runtime.h>
#include <cuda_bf16.h>
#include <cstdint>

// ---------------------------------------------------------------------------
// TernaryCNN v2: conv layers exploit scale-invariance of training-mode BN:
// ternary weights become exact {-1,0,+1}; conv2..4 run as im2col + TF32
// tensor-core GEMM (mma.sync m16n8k8). Conv outputs are C-major [co][n][h][w],
// BN+ReLU+pool fused and permuting back to NCHW.
// ---------------------------------------------------------------------------

#define N_BATCH 32
#define NB_RED 512
#define BN_NB 64

// -------------------- device scratch (static, no allocs) -------------------
__device__ float g_conv[33554432];     // conv output C-major; max 64*32*16384
__device__ float g_pool[8388608];      // pooled NCHW; max 32*64*64*64
__device__ float g_xc[75497472];       // im2col: max 576 x 131072
__device__ float g_tw2[73728];
__device__ float g_tw3[294912];
__device__ float g_tw4[1179648];
__device__ float g_tw1[1728];
__device__ float g_tfw1[33554432];     // 1024*32768
__device__ float g_tfw2[1024000];      // 1000*1024
__device__ float g_fc1[32 * 1024];
__device__ float g_fc1part[16 * 32 * 1024];
__device__ float g_part1[NB_RED];
__device__ float g_part2[NB_RED];
__device__ float g_scal[4];            // [0]=delta [1]=alpha [2]=mean|w|
__device__ float g_bnp1[512 * BN_NB];
__device__ float g_bnp2[512 * BN_NB];
__device__ float g_bnscale[512];
__device__ float g_bnshift[512];

// ----------------------------- ternarize -----------------------------------
__global__ void abs_sum_kernel(const float* __restrict__ w, long n, float* __restrict__ part) {
    __shared__ float sh[256];
    float a = 0.f;
    for (long i = (long)blockIdx.x * 256 + threadIdx.x; i < n; i += (long)NB_RED * 256)
        a += fabsf(w[i]);
    sh[threadIdx.x] = a; __syncthreads();
    for (int o = 128; o > 0; o >>= 1) {
        if (threadIdx.x < o) sh[threadIdx.x] += sh[threadIdx.x + o];
        __syncthreads();
    }
    if (threadIdx.x == 0) part[blockIdx.x] = sh[0];
}

__global__ void delta_final_kernel(const float* __restrict__ part, float inv_n, float* __restrict__ scal) {
    __shared__ float sh[256];
    float a = part[threadIdx.x] + part[threadIdx.x + 256];
    sh[threadIdx.x] = a; __syncthreads();
    for (int o = 128; o > 0; o >>= 1) {
        if (threadIdx.x < o) sh[threadIdx.x] += sh[threadIdx.x + o];
        __syncthreads();
    }
    if (threadIdx.x == 0) {
        float mean = sh[0] * inv_n;
        scal[0] = 0.7f * mean;
        scal[2] = mean;
    }
}

__global__ void masked_sum_kernel(const float* __restrict__ w, long n, const float* __restrict__ scal,
                                  float* __restrict__ p1, float* __restrict__ p2) {
    __shared__ float sh1[256], sh2[256];
    const float delta = scal[0];
    float s = 0.f, c = 0.f;
    for (long i = (long)blockIdx.x * 256 + threadIdx.x; i < n; i += (long)NB_RED * 256) {
        float v = fabsf(w[i]);
        if (v > delta) { s += v; c += 1.f; }
    }
    sh1[threadIdx.x] = s; sh2[threadIdx.x] = c; __syncthreads();
    for (int o = 128; o > 0; o >>= 1) {
        if (threadIdx.x < o) { sh1[threadIdx.x] += sh1[threadIdx.x + o]; sh2[threadIdx.x] += sh2[threadIdx.x + o]; }
        __syncthreads();
    }
    if (threadIdx.x == 0) { p1[blockIdx.x] = sh1[0]; p2[blockIdx.x] = sh2[0]; }
}

__global__ void alpha_final_kernel(const float* __restrict__ p1, const float* __restrict__ p2,
                                   float* __restrict__ scal) {
    __shared__ float sh1[256], sh2[256];
    sh1[threadIdx.x] = p1[threadIdx.x] + p1[threadIdx.x + 256];
    sh2[threadIdx.x] = p2[threadIdx.x] + p2[threadIdx.x + 256];
    __syncthreads();
    for (int o = 128; o > 0; o >>= 1) {
        if (threadIdx.x < o) { sh1[threadIdx.x] += sh1[threadIdx.x + o]; sh2[threadIdx.x] += sh2[threadIdx.x + o]; }
        __syncthreads();
    }
    if (threadIdx.x == 0)
        scal[1] = (sh2[0] > 0.f) ? (sh1[0] / sh2[0]) : scal[2];
}

// FC variant: write {-a, 0, +a}
__global__ void tern_write_kernel(const float* __restrict__ w, long n, const float* __restrict__ scal,
                                  float* __restrict__ out) {
    const float d = scal[0], a = scal[1];
    for (long i = (long)blockIdx.x * 256 + threadIdx.x; i < n; i += (long)gridDim.x * 256) {
        float v = w[i];
        out[i] = (v > d) ? a : ((v < -d) ? -a : 0.f);
    }
}

// Conv variant: write {-1, 0, +1} (scale cancels in batch-stat BN)
__global__ void tern_sign_kernel(const float* __restrict__ w, long n, const float* __restrict__ scal,
                                 float* __restrict__ out) {
    const float d = scal[0];
    for (long i = (long)blockIdx.x * 256 + threadIdx.x; i < n; i += (long)gridDim.x * 256) {
        float v = w[i];
        out[i] = (v > d) ? 1.f : ((v < -d) ? -1.f : 0.f);
    }
}

// ------------------------------ im2col -------------------------------------
__device__ __forceinline__ float to_tf32(float x) {
    uint32_t u;
    asm("cvt.rna.tf32.f32 %0, %1;" : "=r"(u) : "f"(x));
    return __uint_as_float(u);
}

// xc[k][p], k = ci*9 + kh*3 + kw, p = ((n*H + h)*W + w). blockIdx.y = k.
__global__ void im2col_kernel(const float* __restrict__ x, float* __restrict__ xc,
                              int C, int H, int W) {
    const int k = blockIdx.y;
    const int ci = k / 9;
    const int r = (k % 9) / 3 - 1;
    const int s = (k % 3) - 1;
    const int HW = H * W;
    const int p = blockIdx.x * 256 + threadIdx.x;   // grid.x = 32*HW/256
    const int n = p / HW;
    const int rem = p - n * HW;
    const int h = rem / W;
    const int w = rem - h * W;
    const int hh = h + r, ww = w + s;
    float v = 0.f;
    if (hh >= 0 && hh < H && ww >= 0 && ww < W)
        v = x[((long)(n * C + ci) * H + hh) * W + ww];
    xc[(long)k * (32L * HW) + p] = to_tf32(v);
}

// -------------------------- TF32 GEMM (mma.sync) ---------------------------
// C[M][N] = A[M][K] * B[K][N]. A row-major (weights, exact tf32 values),
// B row-major (im2col, pre-rounded to tf32). Block tile 64x128, K-chunk 32,
// 8 warps (2x4), warp tile 32x32, mma m16n8k8.
#define GMT 64
#define GNT 128
#define GKT 32
#define SA_LD 36
#define SB_LD 136
#define SA_BUF (GMT * SA_LD)
#define SB_BUF (GKT * SB_LD)

__device__ __forceinline__ void mma_tf32(float& c0, float& c1, float& c2, float& c3,
                                         uint32_t a0, uint32_t a1, uint32_t a2, uint32_t a3,
                                         uint32_t b0, uint32_t b1) {
    asm volatile(
        "mma.sync.aligned.m16n8k8.row.col.f32.tf32.tf32.f32 "
        "{%0,%1,%2,%3}, {%4,%5,%6,%7}, {%8,%9}, {%0,%1,%2,%3};"
        : "+f"(c0), "+f"(c1), "+f"(c2), "+f"(c3)
        : "r"(a0), "r"(a1), "r"(a2), "r"(a3), "r"(b0), "r"(b1));
}

__global__ void __launch_bounds__(256) gemm_tf32_kernel(
    const float* __restrict__ A, const float* __restrict__ B, float* __restrict__ C,
    int M, int N, int K) {
    extern __shared__ float smem[];
    float* sA = smem;                    // [2][GMT][SA_LD]
    float* sB = smem + 2 * SA_BUF;       // [2][GKT][SB_LD]

    const int tid = threadIdx.x;
    const int warp = tid >> 5, lane = tid & 31;
    const int wm = warp >> 2, wn = warp & 3;
    const int g = lane >> 2, tg = lane & 3;
    const int m0 = blockIdx.y * GMT;
    const int n0 = blockIdx.x * GNT;

    float acc[2][4][4];
#pragma unroll
    for (int mi = 0; mi < 2; mi++)
#pragma unroll
        for (int ni = 0; ni < 4; ni++)
#pragma unroll
            for (int q = 0; q < 4; q++) acc[mi][ni][q] = 0.f;

    const int nk = K / GKT;

    // gmem load helpers: A 2 float4/thread, B 4 float4/thread
    const int a_r0 = tid >> 3, a_c0 = (tid & 7) * 4;          // +256: row+32
    const int b_r0 = tid >> 6, b_c0 = (tid & 63) * 2;         // 2 floats? no:
    // B: 1024 float4 / 256 threads -> 4 each: q=tid+i*256, row=q>>5, c4=q&31

    float4 ra[2], rb[4];

    auto gload = [&](int kc) {
#pragma unroll
        for (int i = 0; i < 2; i++) {
            int q = tid + i * 256;
            int r = q >> 3, c4 = q & 7;
            ra[i] = *(const float4*)&A[(long)(m0 + r) * K + kc * GKT + c4 * 4];
        }
#pragma unroll
        for (int i = 0; i < 4; i++) {
            int q = tid + i * 256;
            int r = q >> 5, c4 = q & 31;
            rb[i] = *(const float4*)&B[(long)(kc * GKT + r) * N + n0 + c4 * 4];
        }
    };
    auto sstore = [&](int buf) {
        float* dA = sA + buf * SA_BUF;
        float* dB = sB + buf * SB_BUF;
#pragma unroll
        for (int i = 0; i < 2; i++) {
            int q = tid + i * 256;
            int r = q >> 3, c4 = q & 7;
            *(float4*)&dA[r * SA_LD + c4 * 4] = ra[i];
        }
#pragma unroll
        for (int i = 0; i < 4; i++) {
            int q = tid + i * 256;
            int r = q >> 5, c4 = q & 31;
            *(float4*)&dB[r * SB_LD + c4 * 4] = rb[i];
        }
    };

    gload(0);
    sstore(0);
    __syncthreads();

    for (int kc = 0; kc < nk; kc++) {
        const int buf = kc & 1;
        if (kc + 1 < nk) gload(kc + 1);

        const float* cA = sA + buf * SA_BUF;
        const float* cB = sB + buf * SB_BUF;
#pragma unroll
        for (int ks = 0; ks < 4; ks++) {
            uint32_t af[2][4], bf[4][2];
#pragma unroll
            for (int mi = 0; mi < 2; mi++) {
                const float* p = cA + (wm * 32 + mi * 16 + g) * SA_LD + ks * 8 + tg;
                af[mi][0] = __float_as_uint(p[0]);
                af[mi][1] = __float_as_uint(p[8 * SA_LD]);
                af[mi][2] = __float_as_uint(p[4]);
                af[mi][3] = __float_as_uint(p[8 * SA_LD + 4]);
            }
#pragma unroll
            for (int ni = 0; ni < 4; ni++) {
                const float* p = cB + (ks * 8 + tg) * SB_LD + wn * 32 + ni * 8 + g;
                bf[ni][0] = __float_as_uint(p[0]);
                bf[ni][1] = __float_as_uint(p[4 * SB_LD]);
            }
#pragma unroll
            for (int mi = 0; mi < 2; mi++)
#pragma unroll
                for (int ni = 0; ni < 4; ni++)
                    mma_tf32(acc[mi][ni][0], acc[mi][ni][1], acc[mi][ni][2], acc[mi][ni][3],
                             af[mi][0], af[mi][1], af[mi][2], af[mi][3],
                             bf[ni][0], bf[ni][1]);
        }
        if (kc + 1 < nk) sstore(buf ^ 1);
        __syncthreads();
    }

#pragma unroll
    for (int mi = 0; mi < 2; mi++) {
        const int row = m0 + wm * 32 + mi * 16 + g;
#pragma unroll
        for (int ni = 0; ni < 4; ni++) {
            const int col = n0 + wn * 32 + ni * 8 + 2 * tg;
            float* p0 = &C[(long)row * N + col];
            p0[0] = acc[mi][ni][0];
            p0[1] = acc[mi][ni][1];
            float* p1 = &C[(long)(row + 8) * N + col];
            p1[0] = acc[mi][ni][2];
            p1[1] = acc[mi][ni][3];
        }
    }
}

// ------------------------------- conv1 direct ------------------------------
// Output C-major: [co][n][h][w]
template <int TILE>
__global__ void conv3x3_kernel(const float* __restrict__ in, const float* __restrict__ wt,
                               float* __restrict__ out, int CI, int CO, int H, int W) {
    constexpr int TD = TILE / 2;
    constexpr int NT = TD * TD;
    __shared__ float s_in[TILE + 2][TILE + 4];
    __shared__ float s_w[8][9];

    const int cogs = CO >> 3;
    const int n = blockIdx.z / cogs;
    const int cog = blockIdx.z % cogs;
    const int h0 = blockIdx.y * TILE;
    const int w0 = blockIdx.x * TILE;
    const int tid = threadIdx.y * TD + threadIdx.x;
    const long HW = (long)H * W;

    float acc[8][4];
#pragma unroll
    for (int j = 0; j < 8; j++)
#pragma unroll
        for (int p = 0; p < 4; p++) acc[j][p] = 0.f;

    for (int ci = 0; ci < CI; ci++) {
        const float* ip = in + ((long)n * CI + ci) * HW;
        for (int idx = tid; idx < (TILE + 2) * (TILE + 2); idx += NT) {
            int r = idx / (TILE + 2), c = idx % (TILE + 2);
            int gh = h0 - 1 + r, gw = w0 - 1 + c;
            float v = 0.f;
            if (gh >= 0 && gh < H && gw >= 0 && gw < W) v = ip[(long)gh * W + gw];
            s_in[r][c] = v;
        }
        for (int idx = tid; idx < 72; idx += NT) {
            int j = idx / 9, k = idx % 9;
            s_w[j][k] = wt[((long)(cog * 8 + j) * CI + ci) * 9 + k];
        }
        __syncthreads();

        float v[4][4];
        const int r0 = threadIdx.y * 2, c0 = threadIdx.x * 2;
#pragma unroll
        for (int r = 0; r < 4; r++)
#pragma unroll
            for (int c = 0; c < 4; c++) v[r][c] = s_in[r0 + r][c0 + c];

#pragma unroll
        for (int j = 0; j < 8; j++) {
            float w00 = s_w[j][0], w01 = s_w[j][1], w02 = s_w[j][2];
            float w10 = s_w[j][3], w11 = s_w[j][4], w12 = s_w[j][5];
            float w20 = s_w[j][6], w21 = s_w[j][7], w22 = s_w[j][8];
#pragma unroll
            for (int dy = 0; dy < 2; dy++)
#pragma unroll
                for (int dx = 0; dx < 2; dx++) {
                    acc[j][dy * 2 + dx] +=
                        v[dy][dx] * w00 + v[dy][dx + 1] * w01 + v[dy][dx + 2] * w02 +
                        v[dy + 1][dx] * w10 + v[dy + 1][dx + 1] * w11 + v[dy + 1][dx + 2] * w12 +
                        v[dy + 2][dx] * w20 + v[dy + 2][dx + 1] * w21 + v[dy + 2][dx + 2] * w22;
                }
        }
        __syncthreads();
    }

    const int r0 = threadIdx.y * 2, c0 = threadIdx.x * 2;
#pragma unroll
    for (int j = 0; j < 8; j++) {
        const long ob = ((long)(cog * 8 + j) * N_BATCH + n) * HW;   // C-major
#pragma unroll
        for (int dy = 0; dy < 2; dy++)
#pragma unroll
            for (int dx = 0; dx < 2; dx++) {
                int h = h0 + r0 + dy, w = w0 + c0 + dx;
                if (h < H && w < W) out[ob + (long)h * W + w] = acc[j][dy * 2 + dx];
            }
    }
}

// ------------------------------ batchnorm ----------------------------------
// conv buffer is C-major: per channel `cnt` contiguous floats.
__global__ void bn_partial_cm_kernel(const float* __restrict__ y, long cnt,
                                     float* __restrict__ p1, float* __restrict__ p2) {
    __shared__ float sh1[256], sh2[256];
    const float* base = y + (long)blockIdx.x * cnt;
    float s = 0.f, s2 = 0.f;
    for (long p = (long)blockIdx.y * 256 + threadIdx.x; p < cnt; p += (long)BN_NB * 256) {
        float v = base[p];
        s += v; s2 += v * v;
    }
    sh1[threadIdx.x] = s; sh2[threadIdx.x] = s2; __syncthreads();
    for (int o = 128; o > 0; o >>= 1) {
        if (threadIdx.x < o) { sh1[threadIdx.x] += sh1[threadIdx.x + o]; sh2[threadIdx.x] += sh2[threadIdx.x + o]; }
        __syncthreads();
    }
    if (threadIdx.x == 0) {
        p1[blockIdx.x * BN_NB + blockIdx.y] = sh1[0];
        p2[blockIdx.x * BN_NB + blockIdx.y] = sh2[0];
    }
}

__global__ void bn_final_kernel(const float* __restrict__ p1, const float* __restrict__ p2, float invM,
                                const float* __restrict__ gamma, const float* __restrict__ beta,
                                float* __restrict__ scale, float* __restrict__ shift) {
    __shared__ float sh1[64], sh2[64];
    const int c = blockIdx.x;
    sh1[threadIdx.x] = p1[c * BN_NB + threadIdx.x];
    sh2[threadIdx.x] = p2[c * BN_NB + threadIdx.x];
    __syncthreads();
    for (int o = 32; o > 0; o >>= 1) {
        if (threadIdx.x < o) { sh1[threadIdx.x] += sh1[threadIdx.x + o]; sh2[threadIdx.x] += sh2[threadIdx.x + o]; }
        __syncthreads();
    }
    if (threadIdx.x == 0) {
        float mean = sh1[0] * invM;
        float var = sh2[0] * invM - mean * mean;
        float istd = rsqrtf(var + 1e-5f);
        float sc = gamma[c] * istd;
        scale[c] = sc;
        shift[c] = beta[c] - mean * sc;
    }
}

// read C-major conv buffer, write pooled NCHW
__global__ void bn_relu_pool_cm_kernel(const float* __restrict__ y, const float* __restrict__ scale,
                                       const float* __restrict__ shift, float* __restrict__ out,
                                       int C, int H, int W, long total) {
    long idx = (long)blockIdx.x * 256 + threadIdx.x;
    if (idx >= total) return;
    const int W2 = W >> 1, H2 = H >> 1;
    int wo = (int)(idx % W2);
    long t = idx / W2;
    int ho = (int)(t % H2); t /= H2;
    int c = (int)(t % C);
    int n = (int)(t / C);
    const float* yp = y + (((long)c * N_BATCH + n) * H + 2 * ho) * W + 2 * wo;
    float sc = scale[c], sh = shift[c];
    float a = fmaxf(sc * yp[0] + sh, sc * yp[1] + sh);
    float b = fmaxf(sc * yp[W] + sh, sc * yp[W + 1] + sh);
    out[idx] = fmaxf(fmaxf(a, b), 0.f);
}

// --------------------------------- FC --------------------------------------
__global__ void fc1_partial_kernel(const float* __restrict__ x, const float* __restrict__ w,
                                   float* __restrict__ part) {
    __shared__ float s_w[64][33];
    __shared__ __align__(16) float s_x[32][34];
    const int K = 32768;
    const int o0 = blockIdx.x * 64;
    const int k0 = blockIdx.y * 2048;
    const int tid = threadIdx.x;
    const int tx = tid & 15;
    const int ty = tid >> 4;

    float acc[4][2];
#pragma unroll
    for (int i = 0; i < 4; i++) { acc[i][0] = 0.f; acc[i][1] = 0.f; }

    for (int kk = k0; kk < k0 + 2048; kk += 32) {
#pragma unroll
        for (int t = 0; t < 8; t++) {
            int idx = tid + t * 256;
            int row = idx >> 5, col = idx & 31;
            s_w[row][col] = w[(long)(o0 + row) * K + kk + col];
        }
#pragma unroll
        for (int t = 0; t < 4; t++) {
            int idx = tid + t * 256;
            int b = idx >> 5, col = idx & 31;
            s_x[col][b] = x[(long)b * K + kk + col];
        }
        __syncthreads();
#pragma unroll
        for (int j = 0; j < 32; j++) {
            float2 xb = *(const float2*)&s_x[j][tx * 2];
#pragma unroll
            for (int i = 0; i < 4; i++) {
                float wv = s_w[ty * 4 + i][j];
                acc[i][0] += wv * xb.x;
                acc[i][1] += wv * xb.y;
            }
        }
        __syncthreads();
    }
#pragma unroll
    for (int i = 0; i < 4; i++)
#pragma unroll
        for (int p = 0; p < 2; p++)
            part[((long)blockIdx.y * 32 + tx * 2 + p) * 1024 + o0 + ty * 4 + i] = acc[i][p];
}

__global__ void fc1_post_kernel(const float* __restrict__ part, const float* __restrict__ bias,
                                float* __restrict__ out) {
    int idx = blockIdx.x * 256 + threadIdx.x;
    if (idx >= 32 * 1024) return;
    int o = idx & 1023;
    float s = 0.f;
#pragma unroll
    for (int ks = 0; ks < 16; ks++) s += part[(long)ks * 32 * 1024 + idx];
    out[idx] = fmaxf(s + bias[o], 0.f);
}

__global__ void fc2_kernel(const float* __restrict__ x, const float* __restrict__ w,
                           const float* __restrict__ bias, float* __restrict__ out) {
    int gw = (blockIdx.x * 256 + threadIdx.x) >> 5;
    int lane = threadIdx.x & 31;
    if (gw >= 32 * 1000) return;
    int b = gw / 1000, o = gw % 1000;
    float a = 0.f;
    for (int k = lane; k < 1024; k += 32)
        a += x[b * 1024 + k] * w[o * 1024 + k];
#pragma unroll
    for (int off = 16; off; off >>= 1) a += __shfl_down_sync(0xffffffffu, a, off);
    if (lane == 0) out[b * 1000 + o] = a + bias[o];
}

// ------------------------------- host side ---------------------------------
static void ternarize_fc(const float* w, long n, float* out) {
    float *p1, *p2, *sc;
    cudaGetSymbolAddress((void**)&p1, g_part1);
    cudaGetSymbolAddress((void**)&p2, g_part2);
    cudaGetSymbolAddress((void**)&sc, g_scal);
    abs_sum_kernel<<<NB_RED, 256>>>(w, n, p1);
    delta_final_kernel<<<1, 256>>>(p1, 1.0f / (float)n, sc);
    masked_sum_kernel<<<NB_RED, 256>>>(w, n, sc, p1, p2);
    alpha_final_kernel<<<1, 256>>>(p1, p2, sc);
    int grid = (int)((n + 2047) / 2048);
    if (grid > 4096) grid = 4096;
    if (grid < 1) grid = 1;
    tern_write_kernel<<<grid, 256>>>(w, n, sc, out);
}

static void ternarize_sign(const float* w, long n, float* out) {
    float *p1, *sc;
    cudaGetSymbolAddress((void**)&p1, g_part1);
    cudaGetSymbolAddress((void**)&sc, g_scal);
    abs_sum_kernel<<<NB_RED, 256>>>(w, n, p1);
    delta_final_kernel<<<1, 256>>>(p1, 1.0f / (float)n, sc);
    int grid = (int)((n + 2047) / 2048);
    if (grid > 4096) grid = 4096;
    if (grid < 1) grid = 1;
    tern_sign_kernel<<<grid, 256>>>(w, n, sc, out);
}

static void bn_pool(const float* conv_buf, const float* gamma, const float* beta,
                    float* pool_buf, int CO, int H, int W) {
    float *bp1, *bp2, *bsc, *bsh;
    cudaGetSymbolAddress((void**)&bp1, g_bnp1);
    cudaGetSymbolAddress((void**)&bp2, g_bnp2);
    cudaGetSymbolAddress((void**)&bsc, g_bnscale);
    cudaGetSymbolAddress((void**)&bsh, g_bnshift);
    const long cnt = (long)N_BATCH * H * W;
    bn_partial_cm_kernel<<<dim3(CO, BN_NB), 256>>>(conv_buf, cnt, bp1, bp2);
    bn_final_kernel<<<CO, 64>>>(bp1, bp2, 1.0f / (float)cnt, gamma, beta, bsc, bsh);
    long total = (long)N_BATCH * CO * (H / 2) * (W / 2);
    bn_relu_pool_cm_kernel<<<(int)((total + 255) / 256), 256>>>(conv_buf, bsc, bsh, pool_buf, CO, H, W, total);
}

// conv via im2col + tf32 GEMM (for layers 2-4)
static void conv_gemm_block(const float* in, const float* tw, const float* gamma, const float* beta,
                            float* xc_buf, float* conv_buf, float* pool_buf,
                            int CI, int CO, int H, int W) {
    const int K = CI * 9;
    const int Npix = N_BATCH * H * W;
    im2col_kernel<<<dim3(Npix / 256, K), 256>>>(in, xc_buf, CI, H, W);

    size_t smem = (2 * SA_BUF + 2 * SB_BUF) * sizeof(float);
    cudaFuncSetAttribute(gemm_tf32_kernel, cudaFuncAttributeMaxDynamicSharedMemorySize, (int)smem);
    gemm_tf32_kernel<<<dim3(Npix / GNT, CO / GMT), 256, smem>>>(tw, xc_buf, conv_buf, CO, Npix, K);

    bn_pool(conv_buf, gamma, beta, pool_buf, CO, H, W);
}

extern "C" void kernel_launch(void* const* d_in, const int* in_sizes, int n_in,
                              void* d_out, int out_size) {
    const float* x   = (const float*)d_in[0];
    const float* w1  = (const float*)d_in[1];
    const float* g1  = (const float*)d_in[3];
    const float* be1 = (const float*)d_in[4];
    const float* w2  = (const float*)d_in[5];
    const float* g2  = (const float*)d_in[7];
    const float* be2 = (const float*)d_in[8];
    const float* w3  = (const float*)d_in[9];
    const float* g3  = (const float*)d_in[11];
    const float* be3 = (const float*)d_in[12];
    const float* w4  = (const float*)d_in[13];
    const float* g4  = (const float*)d_in[15];
    const float* be4 = (const float*)d_in[16];
    const float* fw1 = (const float*)d_in[17];
    const float* fb1 = (const float*)d_in[18];
    const float* fw2 = (const float*)d_in[19];
    const float* fb2 = (const float*)d_in[20];
    float* out = (float*)d_out;

    float *p_conv, *p_pool, *p_xc, *p_tw1, *p_tw2, *p_tw3, *p_tw4, *p_tfw1, *p_tfw2;
    float *p_fc1, *p_fc1part;
    cudaGetSymbolAddress((void**)&p_conv, g_conv);
    cudaGetSymbolAddress((void**)&p_pool, g_pool);
    cudaGetSymbolAddress((void**)&p_xc, g_xc);
    cudaGetSymbolAddress((void**)&p_tw1, g_tw1);
    cudaGetSymbolAddress((void**)&p_tw2, g_tw2);
    cudaGetSymbolAddress((void**)&p_tw3, g_tw3);
    cudaGetSymbolAddress((void**)&p_tw4, g_tw4);
    cudaGetSymbolAddress((void**)&p_tfw1, g_tfw1);
    cudaGetSymbolAddress((void**)&p_tfw2, g_tfw2);
    cudaGetSymbolAddress((void**)&p_fc1, g_fc1);
    cudaGetSymbolAddress((void**)&p_fc1part, g_fc1part);

    // 1) ternarize: conv weights as {-1,0,+1} (BN scale-invariance), FC with alpha
    ternarize_sign(w1, (long)in_sizes[1], p_tw1);
    ternarize_sign(w2, (long)in_sizes[5], p_tw2);
    ternarize_sign(w3, (long)in_sizes[9], p_tw3);
    ternarize_sign(w4, (long)in_sizes[13], p_tw4);
    ternarize_fc(fw1, (long)in_sizes[17], p_tfw1);
    ternarize_fc(fw2, (long)in_sizes[19], p_tfw2);

    // 2) conv1 direct (CI=3), C-major output
    {
        dim3 grid(128 / 32, 128 / 32, N_BATCH * (64 / 8));
        dim3 blk(16, 16);
        conv3x3_kernel<32><<<grid, blk>>>(x, p_tw1, p_conv, 3, 64, 128, 128);
        bn_pool(p_conv, g1, be1, p_pool, 64, 128, 128);
    }

    // 3) conv2-4 via tf32 tensor-core GEMM
    conv_gemm_block(p_pool, p_tw2, g2, be2, p_xc, p_conv, p_pool, 64, 128, 64, 64);
    conv_gemm_block(p_pool, p_tw3, g3, be3, p_xc, p_conv, p_pool, 128, 256, 32, 32);
    conv_gemm_block(p_pool, p_tw4, g4, be4, p_xc, p_conv, p_pool, 256, 512, 16, 16);

    // 4) FC1 (split-K) + relu
    fc1_partial_kernel<<<dim3(16, 16), 256>>>(p_pool, p_tfw1, p_fc1part);
    fc1_post_kernel<<<(32 * 1024 + 255) / 256, 256>>>(p_fc1part, fb1, p_fc1);

    // 5) FC2 -> output
    fc2_kernel<<<(32 * 1000 * 32 + 255) / 256, 256>>>(p_fc1, p_tfw2, fb2, out);
}

// round 5
// speedup vs baseline: 2.6136x; 1.2606x over previous
#include <cuda_runtime.h>
#include <cuda_bf16.h>
#include <cstdint>

// ---------------------------------------------------------------------------
// TernaryCNN v3:
//  - all 4 convs via one implicit-GEMM kernel (fused im2col gather from NCHW)
//  - split-bf16 trick: activation x -> (hi, lo) bf16 pair in adjacent K rows,
//    weights {-1,0,+1} duplicated; mma.m16n8k16.bf16 gives ~2^-18 precision at
//    the cost of one tf32 mma. Weights exact under BN scale-invariance.
//  - FC layers ternarize on the fly (threshold inline, alpha in epilogue).
// ---------------------------------------------------------------------------

#define N_BATCH 32
#define NB_RED 512
#define BN_NB 64

// -------------------- device scratch (static, no allocs) -------------------
__device__ float g_conv[33554432];        // conv out C-major [co][n][h][w]
__device__ float g_pool[8388608];         // pooled NCHW
__device__ uint32_t g_A1[2048];           // packed tern weights 64 x 32
__device__ uint32_t g_A2[73728];          // 128 x 576
__device__ uint32_t g_A3[294912];         // 256 x 1152
__device__ uint32_t g_A4[1179648];        // 512 x 2304
__device__ float g_fc1[32 * 1024];
__device__ float g_fc1part[16 * 32 * 1024];
__device__ float g_part1[NB_RED];
__device__ float g_part2[NB_RED];
__device__ float g_scal[32];              // 8 slots x 4: [0]=delta [1]=alpha [2]=mean
__device__ float g_bnp1[512 * BN_NB];
__device__ float g_bnp2[512 * BN_NB];
__device__ float g_bnscale[512];
__device__ float g_bnshift[512];

// ----------------------------- helpers -------------------------------------
__device__ __forceinline__ uint32_t pack_split(float x) {
    __nv_bfloat16 h = __float2bfloat16_rn(x);
    float hf = __bfloat162float(h);
    __nv_bfloat16 l = __float2bfloat16_rn(x - hf);
    return ((uint32_t)__bfloat16_as_ushort(l) << 16) | (uint32_t)__bfloat16_as_ushort(h);
}

// ----------------------------- ternarize stats ------------------------------
__global__ void abs_sum_kernel(const float* __restrict__ w, long n, float* __restrict__ part) {
    __shared__ float sh[256];
    float a = 0.f;
    for (long i = (long)blockIdx.x * 256 + threadIdx.x; i < n; i += (long)NB_RED * 256)
        a += fabsf(w[i]);
    sh[threadIdx.x] = a; __syncthreads();
    for (int o = 128; o > 0; o >>= 1) {
        if (threadIdx.x < o) sh[threadIdx.x] += sh[threadIdx.x + o];
        __syncthreads();
    }
    if (threadIdx.x == 0) part[blockIdx.x] = sh[0];
}

__global__ void delta_final_kernel(const float* __restrict__ part, float inv_n, float* __restrict__ scal) {
    __shared__ float sh[256];
    float a = part[threadIdx.x] + part[threadIdx.x + 256];
    sh[threadIdx.x] = a; __syncthreads();
    for (int o = 128; o > 0; o >>= 1) {
        if (threadIdx.x < o) sh[threadIdx.x] += sh[threadIdx.x + o];
        __syncthreads();
    }
    if (threadIdx.x == 0) {
        float mean = sh[0] * inv_n;
        scal[0] = 0.7f * mean;
        scal[2] = mean;
    }
}

__global__ void masked_sum_kernel(const float* __restrict__ w, long n, const float* __restrict__ scal,
                                  float* __restrict__ p1, float* __restrict__ p2) {
    __shared__ float sh1[256], sh2[256];
    const float delta = scal[0];
    float s = 0.f, c = 0.f;
    for (long i = (long)blockIdx.x * 256 + threadIdx.x; i < n; i += (long)NB_RED * 256) {
        float v = fabsf(w[i]);
        if (v > delta) { s += v; c += 1.f; }
    }
    sh1[threadIdx.x] = s; sh2[threadIdx.x] = c; __syncthreads();
    for (int o = 128; o > 0; o >>= 1) {
        if (threadIdx.x < o) { sh1[threadIdx.x] += sh1[threadIdx.x + o]; sh2[threadIdx.x] += sh2[threadIdx.x + o]; }
        __syncthreads();
    }
    if (threadIdx.x == 0) { p1[blockIdx.x] = sh1[0]; p2[blockIdx.x] = sh2[0]; }
}

__global__ void alpha_final_kernel(const float* __restrict__ p1, const float* __restrict__ p2,
                                   float* __restrict__ scal) {
    __shared__ float sh1[256], sh2[256];
    sh1[threadIdx.x] = p1[threadIdx.x] + p1[threadIdx.x + 256];
    sh2[threadIdx.x] = p2[threadIdx.x] + p2[threadIdx.x + 256];
    __syncthreads();
    for (int o = 128; o > 0; o >>= 1) {
        if (threadIdx.x < o) { sh1[threadIdx.x] += sh1[threadIdx.x + o]; sh2[threadIdx.x] += sh2[threadIdx.x + o]; }
        __syncthreads();
    }
    if (threadIdx.x == 0)
        scal[1] = (sh2[0] > 0.f) ? (sh1[0] / sh2[0]) : scal[2];
}

// pack conv weights as duplicated bf16 pairs, K-padded to multiple of 32
__global__ void tern_pack_kernel(const float* __restrict__ w, int CO, int K, int Kpad,
                                 const float* __restrict__ scal, uint32_t* __restrict__ out) {
    int idx = blockIdx.x * 256 + threadIdx.x;
    if (idx >= CO * Kpad) return;
    int co = idx / Kpad;
    int kg = idx - co * Kpad;
    float s = 0.f;
    if (kg < K) {
        float v = w[co * K + kg];
        float d = scal[0];
        s = (v > d) ? 1.f : ((v < -d) ? -1.f : 0.f);
    }
    uint32_t u = (uint32_t)__bfloat16_as_ushort(__float2bfloat16_rn(s));
    out[idx] = u * 0x00010001u;
}

// ----------------- implicit-GEMM conv (split-bf16, mma m16n8k16) ------------
// C[co][p] = sum_kg A[co][kg] * x[ci(kg)][h(p)+r(kg)][w(p)+s(kg)]
// A: packed dup-bf16 [CO][Kpad]; B gathered from NCHW x, packed (hi,lo) bf16.
#define GMT 64
#define GNT 128
#define SA_LD 36
#define SB_LD 136
#define SA_BUF (GMT * SA_LD)
#define SB_BUF (32 * SB_LD)

__device__ __forceinline__ void mma_bf16(float& c0, float& c1, float& c2, float& c3,
                                         uint32_t a0, uint32_t a1, uint32_t a2, uint32_t a3,
                                         uint32_t b0, uint32_t b1) {
    asm volatile(
        "mma.sync.aligned.m16n8k16.row.col.f32.bf16.bf16.f32 "
        "{%0,%1,%2,%3}, {%4,%5,%6,%7}, {%8,%9}, {%0,%1,%2,%3};"
        : "+f"(c0), "+f"(c1), "+f"(c2), "+f"(c3)
        : "r"(a0), "r"(a1), "r"(a2), "r"(a3), "r"(b0), "r"(b1));
}

__global__ void __launch_bounds__(256) gemm_conv_kernel(
    const uint32_t* __restrict__ A, const float* __restrict__ X, float* __restrict__ C,
    int CI, int K, int nk, int lw, int lhw, int N) {
    extern __shared__ uint32_t smem_u[];
    uint32_t* sA = smem_u;
    uint32_t* sB = smem_u + 2 * SA_BUF;

    const int tid = threadIdx.x;
    const int warp = tid >> 5, lane = tid & 31;
    const int wm = warp >> 2, wn = warp & 3;
    const int g = lane >> 2, tg = lane & 3;
    const int m0 = blockIdx.y * GMT;
    const int n0 = blockIdx.x * GNT;
    const int Kpad = nk * 32;

    // fixed pixel per thread (for B gather)
    const int col = tid & 127;
    const int khalf = tid >> 7;        // 0: even klog, 1: odd klog
    const int W = 1 << lw;
    const int H = 1 << (lhw - lw);
    const int p = n0 + col;
    const int hp = (p >> lw) & (H - 1);
    const int wp = p & (W - 1);
    const float* xb = X + (((long)(p >> lhw) * CI) << lhw);

    float acc[2][4][4];
#pragma unroll
    for (int mi = 0; mi < 2; mi++)
#pragma unroll
        for (int ni = 0; ni < 4; ni++)
#pragma unroll
            for (int q = 0; q < 4; q++) acc[mi][ni][q] = 0.f;

    uint4 rA[2];
    uint32_t rbw[16];

    auto gload = [&](int kc) {
#pragma unroll
        for (int i = 0; i < 2; i++) {
            int q = tid + i * 256;
            int r = q >> 3, c4 = q & 7;
            rA[i] = *(const uint4*)&A[(long)(m0 + r) * Kpad + kc * 32 + c4 * 4];
        }
        int base = kc * 32 + khalf;
        int ci = base / 9;
        int rs = base - ci * 9;
#pragma unroll
        for (int i = 0; i < 16; i++) {
            int kg = base + 2 * i;
            int rr = rs / 3;
            int ss = rs - rr * 3;
            int hh = hp + rr - 1;
            int ww = wp + ss - 1;
            float v = 0.f;
            if (kg < K && (unsigned)hh < (unsigned)H && (unsigned)ww < (unsigned)W)
                v = xb[(ci << lhw) + (hh << lw) + ww];
            rbw[i] = pack_split(v);
            // advance (ci, rs) by 2
            rs += 2;
            if (rs >= 9) { rs -= 9; ci++; }
        }
    };
    auto sstore = [&](int buf) {
        uint32_t* dA = sA + buf * SA_BUF;
        uint32_t* dB = sB + buf * SB_BUF;
#pragma unroll
        for (int i = 0; i < 2; i++) {
            int q = tid + i * 256;
            int r = q >> 3, c4 = q & 7;
            *(uint4*)&dA[r * SA_LD + c4 * 4] = rA[i];
        }
#pragma unroll
        for (int i = 0; i < 16; i++)
            dB[(khalf + 2 * i) * SB_LD + col] = rbw[i];
    };

    gload(0);
    sstore(0);
    __syncthreads();

    for (int kc = 0; kc < nk; kc++) {
        const int buf = kc & 1;
        if (kc + 1 < nk) gload(kc + 1);

        const uint32_t* cA = sA + buf * SA_BUF;
        const uint32_t* cB = sB + buf * SB_BUF;
#pragma unroll
        for (int ks = 0; ks < 4; ks++) {
            uint32_t af[2][4], bf[4][2];
#pragma unroll
            for (int mi = 0; mi < 2; mi++) {
                const uint32_t* pa = cA + (wm * 32 + mi * 16 + g) * SA_LD + ks * 8 + tg;
                af[mi][0] = pa[0];
                af[mi][1] = pa[8 * SA_LD];
                af[mi][2] = pa[4];
                af[mi][3] = pa[8 * SA_LD + 4];
            }
#pragma unroll
            for (int ni = 0; ni < 4; ni++) {
                const uint32_t* pb = cB + (ks * 8 + tg) * SB_LD + wn * 32 + ni * 8 + g;
                bf[ni][0] = pb[0];
                bf[ni][1] = pb[4 * SB_LD];
            }
#pragma unroll
            for (int mi = 0; mi < 2; mi++)
#pragma unroll
                for (int ni = 0; ni < 4; ni++)
                    mma_bf16(acc[mi][ni][0], acc[mi][ni][1], acc[mi][ni][2], acc[mi][ni][3],
                             af[mi][0], af[mi][1], af[mi][2], af[mi][3],
                             bf[ni][0], bf[ni][1]);
        }
        if (kc + 1 < nk) sstore(buf ^ 1);
        __syncthreads();
    }

#pragma unroll
    for (int mi = 0; mi < 2; mi++) {
        const int row = m0 + wm * 32 + mi * 16 + g;
#pragma unroll
        for (int ni = 0; ni < 4; ni++) {
            const int colc = n0 + wn * 32 + ni * 8 + 2 * tg;
            float* p0 = &C[(long)row * N + colc];
            p0[0] = acc[mi][ni][0];
            p0[1] = acc[mi][ni][1];
            float* p1 = &C[(long)(row + 8) * N + colc];
            p1[0] = acc[mi][ni][2];
            p1[1] = acc[mi][ni][3];
        }
    }
}

// ------------------------------ batchnorm ----------------------------------
__global__ void bn_partial_cm_kernel(const float* __restrict__ y, long cnt,
                                     float* __restrict__ p1, float* __restrict__ p2) {
    __shared__ float sh1[256], sh2[256];
    const float* base = y + (long)blockIdx.x * cnt;
    float s = 0.f, s2 = 0.f;
    for (long p = (long)blockIdx.y * 256 + threadIdx.x; p < cnt; p += (long)BN_NB * 256) {
        float v = base[p];
        s += v; s2 += v * v;
    }
    sh1[threadIdx.x] = s; sh2[threadIdx.x] = s2; __syncthreads();
    for (int o = 128; o > 0; o >>= 1) {
        if (threadIdx.x < o) { sh1[threadIdx.x] += sh1[threadIdx.x + o]; sh2[threadIdx.x] += sh2[threadIdx.x + o]; }
        __syncthreads();
    }
    if (threadIdx.x == 0) {
        p1[blockIdx.x * BN_NB + blockIdx.y] = sh1[0];
        p2[blockIdx.x * BN_NB + blockIdx.y] = sh2[0];
    }
}

__global__ void bn_final_kernel(const float* __restrict__ p1, const float* __restrict__ p2, float invM,
                                const float* __restrict__ gamma, const float* __restrict__ beta,
                                float* __restrict__ scale, float* __restrict__ shift) {
    __shared__ float sh1[64], sh2[64];
    const int c = blockIdx.x;
    sh1[threadIdx.x] = p1[c * BN_NB + threadIdx.x];
    sh2[threadIdx.x] = p2[c * BN_NB + threadIdx.x];
    __syncthreads();
    for (int o = 32; o > 0; o >>= 1) {
        if (threadIdx.x < o) { sh1[threadIdx.x] += sh1[threadIdx.x + o]; sh2[threadIdx.x] += sh2[threadIdx.x + o]; }
        __syncthreads();
    }
    if (threadIdx.x == 0) {
        float mean = sh1[0] * invM;
        float var = sh2[0] * invM - mean * mean;
        float istd = rsqrtf(var + 1e-5f);
        float sc = gamma[c] * istd;
        scale[c] = sc;
        shift[c] = beta[c] - mean * sc;
    }
}

__global__ void bn_relu_pool_cm_kernel(const float* __restrict__ y, const float* __restrict__ scale,
                                       const float* __restrict__ shift, float* __restrict__ out,
                                       int C, int H, int W, long total) {
    long idx = (long)blockIdx.x * 256 + threadIdx.x;
    if (idx >= total) return;
    const int W2 = W >> 1, H2 = H >> 1;
    int wo = (int)(idx % W2);
    long t = idx / W2;
    int ho = (int)(t % H2); t /= H2;
    int c = (int)(t % C);
    int n = (int)(t / C);
    const float* yp = y + (((long)c * N_BATCH + n) * H + 2 * ho) * W + 2 * wo;
    float sc = scale[c], sh = shift[c];
    float a = fmaxf(sc * yp[0] + sh, sc * yp[1] + sh);
    float b = fmaxf(sc * yp[W] + sh, sc * yp[W + 1] + sh);
    out[idx] = fmaxf(fmaxf(a, b), 0.f);
}

// --------------------------------- FC --------------------------------------
// FC1 split-K; ternarize fw1 inline with delta, alpha applied in post.
__global__ void fc1_partial_kernel(const float* __restrict__ x, const float* __restrict__ w,
                                   const float* __restrict__ scal, float* __restrict__ part) {
    __shared__ float s_w[64][33];
    __shared__ __align__(16) float s_x[32][34];
    const int K = 32768;
    const int o0 = blockIdx.x * 64;
    const int k0 = blockIdx.y * 2048;
    const int tid = threadIdx.x;
    const int tx = tid & 15;
    const int ty = tid >> 4;
    const float d = scal[0];

    float acc[4][2];
#pragma unroll
    for (int i = 0; i < 4; i++) { acc[i][0] = 0.f; acc[i][1] = 0.f; }

    for (int kk = k0; kk < k0 + 2048; kk += 32) {
#pragma unroll
        for (int t = 0; t < 8; t++) {
            int idx = tid + t * 256;
            int row = idx >> 5, colw = idx & 31;
            float v = w[(long)(o0 + row) * K + kk + colw];
            s_w[row][colw] = (v > d) ? 1.f : ((v < -d) ? -1.f : 0.f);
        }
#pragma unroll
        for (int t = 0; t < 4; t++) {
            int idx = tid + t * 256;
            int b = idx >> 5, colw = idx & 31;
            s_x[colw][b] = x[(long)b * K + kk + colw];
        }
        __syncthreads();
#pragma unroll
        for (int j = 0; j < 32; j++) {
            float2 xv = *(const float2*)&s_x[j][tx * 2];
#pragma unroll
            for (int i = 0; i < 4; i++) {
                float wv = s_w[ty * 4 + i][j];
                acc[i][0] += wv * xv.x;
                acc[i][1] += wv * xv.y;
            }
        }
        __syncthreads();
    }
#pragma unroll
    for (int i = 0; i < 4; i++)
#pragma unroll
        for (int q = 0; q < 2; q++)
            part[((long)blockIdx.y * 32 + tx * 2 + q) * 1024 + o0 + ty * 4 + i] = acc[i][q];
}

__global__ void fc1_post_kernel(const float* __restrict__ part, const float* __restrict__ bias,
                                const float* __restrict__ scal, float* __restrict__ out) {
    int idx = blockIdx.x * 256 + threadIdx.x;
    if (idx >= 32 * 1024) return;
    int o = idx & 1023;
    float s = 0.f;
#pragma unroll
    for (int ks = 0; ks < 16; ks++) s += part[(long)ks * 32 * 1024 + idx];
    out[idx] = fmaxf(s * scal[1] + bias[o], 0.f);
}

__global__ void fc2_kernel(const float* __restrict__ x, const float* __restrict__ w,
                           const float* __restrict__ bias, const float* __restrict__ scal,
                           float* __restrict__ out) {
    int gw = (blockIdx.x * 256 + threadIdx.x) >> 5;
    int lane = threadIdx.x & 31;
    if (gw >= 32 * 1000) return;
    int b = gw / 1000, o = gw % 1000;
    const float d = scal[0];
    float a = 0.f;
    for (int k = lane; k < 1024; k += 32) {
        float wv = w[o * 1024 + k];
        float sg = (wv > d) ? 1.f : ((wv < -d) ? -1.f : 0.f);
        a += x[b * 1024 + k] * sg;
    }
#pragma unroll
    for (int off = 16; off; off >>= 1) a += __shfl_down_sync(0xffffffffu, a, off);
    if (lane == 0) out[b * 1000 + o] = a * scal[1] + bias[o];
}

// ------------------------------- host side ---------------------------------
static float* scal_slot(int slot) {
    float* sc;
    cudaGetSymbolAddress((void**)&sc, g_scal);
    return sc + 4 * slot;
}

static void tern_stats_delta(const float* w, long n, int slot) {
    float* p1;
    cudaGetSymbolAddress((void**)&p1, g_part1);
    abs_sum_kernel<<<NB_RED, 256>>>(w, n, p1);
    delta_final_kernel<<<1, 256>>>(p1, 1.0f / (float)n, scal_slot(slot));
}

static void tern_stats_full(const float* w, long n, int slot) {
    float *p1, *p2;
    cudaGetSymbolAddress((void**)&p1, g_part1);
    cudaGetSymbolAddress((void**)&p2, g_part2);
    tern_stats_delta(w, n, slot);
    masked_sum_kernel<<<NB_RED, 256>>>(w, n, scal_slot(slot), p1, p2);
    alpha_final_kernel<<<1, 256>>>(p1, p2, scal_slot(slot));
}

static void tern_pack(const float* w, int CO, int K, int Kpad, int slot, uint32_t* out) {
    tern_stats_delta(w, (long)CO * K, slot);
    tern_pack_kernel<<<(CO * Kpad + 255) / 256, 256>>>(w, CO, K, Kpad, scal_slot(slot), out);
}

static void bn_pool(const float* conv_buf, const float* gamma, const float* beta,
                    float* pool_buf, int CO, int H, int W) {
    float *bp1, *bp2, *bsc, *bsh;
    cudaGetSymbolAddress((void**)&bp1, g_bnp1);
    cudaGetSymbolAddress((void**)&bp2, g_bnp2);
    cudaGetSymbolAddress((void**)&bsc, g_bnscale);
    cudaGetSymbolAddress((void**)&bsh, g_bnshift);
    const long cnt = (long)N_BATCH * H * W;
    bn_partial_cm_kernel<<<dim3(CO, BN_NB), 256>>>(conv_buf, cnt, bp1, bp2);
    bn_final_kernel<<<CO, 64>>>(bp1, bp2, 1.0f / (float)cnt, gamma, beta, bsc, bsh);
    long total = (long)N_BATCH * CO * (H / 2) * (W / 2);
    bn_relu_pool_cm_kernel<<<(int)((total + 255) / 256), 256>>>(conv_buf, bsc, bsh, pool_buf, CO, H, W, total);
}

static void conv_layer(const float* in, const uint32_t* Apack, const float* gamma, const float* beta,
                       float* conv_buf, float* pool_buf, int CI, int CO, int K, int lw, int lhw) {
    const int N = N_BATCH << lhw;
    const int nk = (K + 31) / 32;
    size_t smem = (size_t)(2 * SA_BUF + 2 * SB_BUF) * 4;
    cudaFuncSetAttribute(gemm_conv_kernel, cudaFuncAttributeMaxDynamicSharedMemorySize, (int)smem);
    gemm_conv_kernel<<<dim3(N / GNT, CO / GMT), 256, smem>>>(Apack, in, conv_buf, CI, K, nk, lw, lhw, N);
    bn_pool(conv_buf, gamma, beta, pool_buf, CO, 1 << (lhw - lw), 1 << lw);
}

extern "C" void kernel_launch(void* const* d_in, const int* in_sizes, int n_in,
                              void* d_out, int out_size) {
    const float* x   = (const float*)d_in[0];
    const float* w1  = (const float*)d_in[1];
    const float* g1  = (const float*)d_in[3];
    const float* be1 = (const float*)d_in[4];
    const float* w2  = (const float*)d_in[5];
    const float* g2  = (const float*)d_in[7];
    const float* be2 = (const float*)d_in[8];
    const float* w3  = (const float*)d_in[9];
    const float* g3  = (const float*)d_in[11];
    const float* be3 = (const float*)d_in[12];
    const float* w4  = (const float*)d_in[13];
    const float* g4  = (const float*)d_in[15];
    const float* be4 = (const float*)d_in[16];
    const float* fw1 = (const float*)d_in[17];
    const float* fb1 = (const float*)d_in[18];
    const float* fw2 = (const float*)d_in[19];
    const float* fb2 = (const float*)d_in[20];
    float* out = (float*)d_out;

    float *p_conv, *p_pool, *p_fc1, *p_fc1part;
    uint32_t *pA1, *pA2, *pA3, *pA4;
    cudaGetSymbolAddress((void**)&p_conv, g_conv);
    cudaGetSymbolAddress((void**)&p_pool, g_pool);
    cudaGetSymbolAddress((void**)&pA1, g_A1);
    cudaGetSymbolAddress((void**)&pA2, g_A2);
    cudaGetSymbolAddress((void**)&pA3, g_A3);
    cudaGetSymbolAddress((void**)&pA4, g_A4);
    cudaGetSymbolAddress((void**)&p_fc1, g_fc1);
    cudaGetSymbolAddress((void**)&p_fc1part, g_fc1part);

    // 1) ternarize conv weights -> packed dup-bf16 sign buffers (scale cancels in BN)
    tern_pack(w1, 64, 27, 32, 0, pA1);
    tern_pack(w2, 128, 576, 576, 1, pA2);
    tern_pack(w3, 256, 1152, 1152, 2, pA3);
    tern_pack(w4, 512, 2304, 2304, 3, pA4);
    // FC stats (delta + alpha); weights used raw in FC kernels
    tern_stats_full(fw1, (long)in_sizes[17], 4);
    tern_stats_full(fw2, (long)in_sizes[19], 5);

    // 2) conv blocks: implicit-GEMM + BN + relu + pool
    conv_layer(x,      pA1, g1, be1, p_conv, p_pool, 3,   64,  27,   7, 14);
    conv_layer(p_pool, pA2, g2, be2, p_conv, p_pool, 64,  128, 576,  6, 12);
    conv_layer(p_pool, pA3, g3, be3, p_conv, p_pool, 128, 256, 1152, 5, 10);
    conv_layer(p_pool, pA4, g4, be4, p_conv, p_pool, 256, 512, 2304, 4, 8);

    // 3) FC1 (split-K, inline ternarize) + relu
    fc1_partial_kernel<<<dim3(16, 16), 256>>>(p_pool, fw1, scal_slot(4), p_fc1part);
    fc1_post_kernel<<<(32 * 1024 + 255) / 256, 256>>>(p_fc1part, fb1, scal_slot(4), p_fc1);

    // 4) FC2 -> output
    fc2_kernel<<<(32 * 1000 * 32 + 255) / 256, 256>>>(p_fc1, fw2, fb2, scal_slot(5), out);
}